// round 1
// baseline (speedup 1.0000x reference)
#include <cuda_runtime.h>

// Problem constants
#define NB 4
#define NS 2048
#define NE 1024
#define NH 16
#define ND 64
#define NM (NB*NS)   // 8192
#define NN (NH*ND)   // 1024

// Scratch: Q,K stored [b,h,d,s] (d-major for conflict-free attention smem loads),
// V stored [b,h,s,d].
__device__ float g_Q[(size_t)NB*NH*NS*ND];
__device__ float g_K[(size_t)NB*NH*NS*ND];
__device__ float g_V[(size_t)NB*NH*NS*ND];

// ---------------------------------------------------------------------------
// Projection GEMM:  out = x @ w^T + bias
//   x: [M=8192, 1024] row-major, w: [1024, 1024] row-major (both K-contiguous)
//   tmode==0: write [b,h,s,d]   tmode==1: write [b,h,d,s]
// Tiles 64x64x16, 256 threads, 4x4 register micro-tile.
// ---------------------------------------------------------------------------
__global__ __launch_bounds__(256) void proj_kernel(
    const float* __restrict__ x, const float* __restrict__ w,
    const float* __restrict__ bias, float* __restrict__ out, int tmode)
{
    __shared__ float As[16][68];   // [k][row], pad 68 -> aligned float4, conflict-free
    __shared__ float Ws[16][68];   // [k][col]
    const int tid = threadIdx.x;
    const int rowBase = blockIdx.y * 64;
    const int colBase = blockIdx.x * 64;
    const int tr = tid >> 4, tc = tid & 15;
    const int lr = tid >> 2, lk = (tid & 3) << 2;

    float acc[4][4] = {};
    const float* xg = x + (size_t)(rowBase + lr) * NE + lk;
    const float* wg = w + (size_t)(colBase + lr) * NE + lk;

    for (int k0 = 0; k0 < NE; k0 += 16) {
        float4 av = *(const float4*)(xg + k0);
        float4 wv = *(const float4*)(wg + k0);
        __syncthreads();
        As[lk+0][lr]=av.x; As[lk+1][lr]=av.y; As[lk+2][lr]=av.z; As[lk+3][lr]=av.w;
        Ws[lk+0][lr]=wv.x; Ws[lk+1][lr]=wv.y; Ws[lk+2][lr]=wv.z; Ws[lk+3][lr]=wv.w;
        __syncthreads();
#pragma unroll
        for (int kk = 0; kk < 16; kk++) {
            float4 a4 = *(const float4*)&As[kk][tr<<2];
            float4 b4 = *(const float4*)&Ws[kk][tc<<2];
            float a[4] = {a4.x, a4.y, a4.z, a4.w};
            float b[4] = {b4.x, b4.y, b4.z, b4.w};
#pragma unroll
            for (int i = 0; i < 4; i++)
#pragma unroll
                for (int j = 0; j < 4; j++)
                    acc[i][j] = fmaf(a[i], b[j], acc[i][j]);
        }
    }

    const int h = colBase >> 6;   // BN == 64 == head dim
    float4 bv = *(const float4*)&bias[colBase + (tc<<2)];
    const float bb4[4] = {bv.x, bv.y, bv.z, bv.w};

    if (tmode == 0) {
#pragma unroll
        for (int i = 0; i < 4; i++) {
            int mrow = rowBase + (tr<<2) + i;
            int bb = mrow >> 11;            // / 2048
            int s  = mrow & (NS - 1);
            float4 r = make_float4(acc[i][0]+bb4[0], acc[i][1]+bb4[1],
                                   acc[i][2]+bb4[2], acc[i][3]+bb4[3]);
            *(float4*)&out[(((size_t)bb*NH + h)*NS + s)*ND + (tc<<2)] = r;
        }
    } else {
#pragma unroll
        for (int i = 0; i < 4; i++) {
            int mrow = rowBase + (tr<<2) + i;
            int bb = mrow >> 11;
            int s  = mrow & (NS - 1);
#pragma unroll
            for (int j = 0; j < 4; j++) {
                int d = (tc<<2) + j;
                out[(((size_t)bb*NH + h)*ND + d)*NS + s] = acc[i][j] + bb4[j];
            }
        }
    }
}

// ---------------------------------------------------------------------------
// Flash attention (causal). One CTA per (b, h, 64-row q tile).
// Q,K read from [b,h,d,s]; V from [b,h,s,d]. fp32, online softmax.
// ---------------------------------------------------------------------------
__global__ __launch_bounds__(256) void attn_kernel(float* __restrict__ out)
{
    extern __shared__ float sm[];
    float* QsT = sm;                   // [64 d][64 row]  stride 64
    float* KsT = sm + 64*64;           // [64 d][68]      stride 68; reused as P[row][68]
    float* Vs  = sm + 64*64 + 64*68;   // [64 jj][64 d]   stride 64

    const int tid = threadIdx.x;
    const int b = blockIdx.z, h = blockIdx.y, qt = blockIdx.x;
    const int tr = tid >> 4, tc = tid & 15;
    const size_t head = ((size_t)b*NH + h) * (size_t)(NS*ND);

    // Load Q tile (already d-major in gmem), scale by 1/sqrt(64)
    {
        const float* Qg = g_Q + head + qt*64;    // element (d, s=qt*64+c)
#pragma unroll
        for (int u = 0; u < 4; u++) {
            int id = tid + u*256;
            int dd = id >> 4;
            int c4 = (id & 15) << 2;
            float4 q = *(const float4*)&Qg[(size_t)dd*NS + c4];
            q.x *= 0.125f; q.y *= 0.125f; q.z *= 0.125f; q.w *= 0.125f;
            *(float4*)&QsT[dd*64 + c4] = q;
        }
    }

    float mx[4], ls[4], o[4][4];
#pragma unroll
    for (int i = 0; i < 4; i++) {
        mx[i] = -1e30f; ls[i] = 0.f;
#pragma unroll
        for (int j = 0; j < 4; j++) o[i][j] = 0.f;
    }

    const int nt = qt + 1;
    for (int kt = 0; kt < nt; kt++) {
        const float* Kg = g_K + head + kt*64;                 // (d, s)
        const float* Vg = g_V + head + (size_t)kt*64*ND;      // (s, d)
        float4 kreg[4], vreg[4];
#pragma unroll
        for (int u = 0; u < 4; u++) {
            int id = tid + u*256;
            int r  = id >> 4;
            int c4 = (id & 15) << 2;
            kreg[u] = *(const float4*)&Kg[(size_t)r*NS + c4];
            vreg[u] = *(const float4*)&Vg[r*ND + c4];
        }
        __syncthreads();   // previous PV / Q-load consumers done before overwrite
#pragma unroll
        for (int u = 0; u < 4; u++) {
            int id = tid + u*256;
            int r  = id >> 4;
            int c4 = (id & 15) << 2;
            *(float4*)&KsT[r*68 + c4] = kreg[u];
            *(float4*)&Vs[r*64 + c4]  = vreg[u];
        }
        __syncthreads();

        // S = Q K^T  (64x64, contraction over d)
        float acc[4][4] = {};
#pragma unroll 8
        for (int d = 0; d < 64; d++) {
            float4 a4 = *(const float4*)&QsT[d*64 + (tr<<2)];
            float4 b4 = *(const float4*)&KsT[d*68 + (tc<<2)];
            float a[4]  = {a4.x, a4.y, a4.z, a4.w};
            float bq[4] = {b4.x, b4.y, b4.z, b4.w};
#pragma unroll
            for (int i = 0; i < 4; i++)
#pragma unroll
                for (int j = 0; j < 4; j++)
                    acc[i][j] = fmaf(a[i], bq[j], acc[i][j]);
        }

        // Causal mask (only diagonal tile can mask)
        if (kt == qt) {
#pragma unroll
            for (int i = 0; i < 4; i++)
#pragma unroll
                for (int j = 0; j < 4; j++)
                    if ((tc<<2)+j > (tr<<2)+i) acc[i][j] = -1e30f;
        }

        // Online softmax; rows owned by 16-lane groups (shfl_xor width 16)
        float sc[4];
#pragma unroll
        for (int i = 0; i < 4; i++) {
            float rm = fmaxf(fmaxf(acc[i][0], acc[i][1]), fmaxf(acc[i][2], acc[i][3]));
            rm = fmaxf(rm, __shfl_xor_sync(0xffffffffu, rm, 1));
            rm = fmaxf(rm, __shfl_xor_sync(0xffffffffu, rm, 2));
            rm = fmaxf(rm, __shfl_xor_sync(0xffffffffu, rm, 4));
            rm = fmaxf(rm, __shfl_xor_sync(0xffffffffu, rm, 8));
            float mn = fmaxf(mx[i], rm);
            sc[i] = __expf(mx[i] - mn);
            mx[i] = mn;
            float rs = 0.f;
#pragma unroll
            for (int j = 0; j < 4; j++) { acc[i][j] = __expf(acc[i][j] - mn); rs += acc[i][j]; }
            rs += __shfl_xor_sync(0xffffffffu, rs, 1);
            rs += __shfl_xor_sync(0xffffffffu, rs, 2);
            rs += __shfl_xor_sync(0xffffffffu, rs, 4);
            rs += __shfl_xor_sync(0xffffffffu, rs, 8);
            ls[i] = ls[i]*sc[i] + rs;
#pragma unroll
            for (int j = 0; j < 4; j++) o[i][j] *= sc[i];
        }

        __syncthreads();   // all score-GEMM reads of KsT complete
        // Write P into the K buffer (now free): P[row][jj], stride 68
#pragma unroll
        for (int i = 0; i < 4; i++)
            *(float4*)&KsT[((tr<<2)+i)*68 + (tc<<2)] =
                make_float4(acc[i][0], acc[i][1], acc[i][2], acc[i][3]);
        __syncthreads();

        // O += P V
#pragma unroll 4
        for (int jj = 0; jj < 64; jj++) {
            float4 v4 = *(const float4*)&Vs[jj*64 + (tc<<2)];
#pragma unroll
            for (int i = 0; i < 4; i++) {
                float pb = KsT[((tr<<2)+i)*68 + jj];
                o[i][0] = fmaf(pb, v4.x, o[i][0]);
                o[i][1] = fmaf(pb, v4.y, o[i][1]);
                o[i][2] = fmaf(pb, v4.z, o[i][2]);
                o[i][3] = fmaf(pb, v4.w, o[i][3]);
            }
        }
    }

    // Epilogue: z[b, s, h*64 + d] = o / l
#pragma unroll
    for (int i = 0; i < 4; i++) {
        int s = qt*64 + (tr<<2) + i;
        float inv = 1.0f / ls[i];
        float4 r = make_float4(o[i][0]*inv, o[i][1]*inv, o[i][2]*inv, o[i][3]*inv);
        *(float4*)&out[((size_t)b*NS + s)*NN + h*ND + (tc<<2)] = r;
    }
}

// ---------------------------------------------------------------------------
extern "C" void kernel_launch(void* const* d_in, const int* in_sizes, int n_in,
                              void* d_out, int out_size)
{
    (void)in_sizes; (void)n_in; (void)out_size;
    const float* x_q  = (const float*)d_in[0];
    const float* x_kv = (const float*)d_in[1];
    // d_in[2] = attn_mask (known causal; applied analytically in-kernel)
    const float* w_q = (const float*)d_in[3];
    const float* b_q = (const float*)d_in[4];
    const float* w_k = (const float*)d_in[5];
    const float* b_k = (const float*)d_in[6];
    const float* w_v = (const float*)d_in[7];
    const float* b_v = (const float*)d_in[8];
    float* out = (float*)d_out;

    float *qp = nullptr, *kp = nullptr, *vp = nullptr;
    cudaGetSymbolAddress((void**)&qp, g_Q);
    cudaGetSymbolAddress((void**)&kp, g_K);
    cudaGetSymbolAddress((void**)&vp, g_V);

    dim3 pg(NN/64, NM/64);
    proj_kernel<<<pg, 256>>>(x_q,  w_q, b_q, qp, 1);  // Q -> [b,h,d,s]
    proj_kernel<<<pg, 256>>>(x_kv, w_k, b_k, kp, 1);  // K -> [b,h,d,s]
    proj_kernel<<<pg, 256>>>(x_kv, w_v, b_v, vp, 0);  // V -> [b,h,s,d]

    const int smem = (64*64 + 64*68 + 64*64) * (int)sizeof(float);  // 50176 B
    cudaFuncSetAttribute(attn_kernel, cudaFuncAttributeMaxDynamicSharedMemorySize, smem);
    attn_kernel<<<dim3(NS/64, NH, NB), 256, smem>>>(out);
}

// round 6
// speedup vs baseline: 1.6784x; 1.6784x over previous
#include <cuda_runtime.h>
#include <cuda_bf16.h>
#include <cstdint>

// Problem constants
#define NB 4
#define NS 2048
#define NE 1024
#define NH 16
#define ND 64
#define NM (NB*NS)   // 8192
#define NN (NH*ND)   // 1024

// fp32 scratch for attention inputs: Q,K in [b,h,d,s]; V in [b,h,s,d]
__device__ float g_Q[(size_t)NB*NH*NS*ND];
__device__ float g_K[(size_t)NB*NH*NS*ND];
__device__ float g_V[(size_t)NB*NH*NS*ND];

// bf16 hi/lo splits of activations and weights
__device__ __nv_bfloat16 g_xq_h [(size_t)NM*NE], g_xq_l [(size_t)NM*NE];
__device__ __nv_bfloat16 g_xkv_h[(size_t)NM*NE], g_xkv_l[(size_t)NM*NE];
__device__ __nv_bfloat16 g_wq_h [(size_t)NN*NE], g_wq_l [(size_t)NN*NE];
__device__ __nv_bfloat16 g_wk_h [(size_t)NN*NE], g_wk_l [(size_t)NN*NE];
__device__ __nv_bfloat16 g_wv_h [(size_t)NN*NE], g_wv_l [(size_t)NN*NE];

// ---------------------------------------------------------------------------
// Helpers (all plain compute_103-legal: cp.async, ldmatrix, mma.sync)
// ---------------------------------------------------------------------------
__device__ __forceinline__ uint32_t smem_u32(const void* p) {
    uint32_t a;
    asm("{ .reg .u64 t; cvta.to.shared.u64 t, %1; cvt.u32.u64 %0, t; }" : "=r"(a) : "l"(p));
    return a;
}
#define CP_ASYNC16(s, g)  asm volatile("cp.async.cg.shared.global [%0], [%1], 16;" :: "r"(s), "l"(g) : "memory")
#define CP_COMMIT()       asm volatile("cp.async.commit_group;" ::: "memory")
#define CP_WAIT1()        asm volatile("cp.async.wait_group 1;" ::: "memory")

__device__ __forceinline__ void ldm_x4(uint32_t* r, uint32_t addr) {
    asm volatile("ldmatrix.sync.aligned.m8n8.x4.shared.b16 {%0,%1,%2,%3}, [%4];"
        : "=r"(r[0]), "=r"(r[1]), "=r"(r[2]), "=r"(r[3]) : "r"(addr));
}
__device__ __forceinline__ void mma16816(float* c, const uint32_t* a, const uint32_t* b) {
    asm volatile("mma.sync.aligned.m16n8k16.row.col.f32.bf16.bf16.f32 "
        "{%0,%1,%2,%3}, {%4,%5,%6,%7}, {%8,%9}, {%0,%1,%2,%3};"
        : "+f"(c[0]), "+f"(c[1]), "+f"(c[2]), "+f"(c[3])
        : "r"(a[0]), "r"(a[1]), "r"(a[2]), "r"(a[3]), "r"(b[0]), "r"(b[1]));
}

// ---------------------------------------------------------------------------
// Split fp32 -> bf16 hi + bf16 lo (x = hi + lo up to ~2^-17 rel)
// ---------------------------------------------------------------------------
__global__ __launch_bounds__(256) void split_kernel(
    const float* __restrict__ in, __nv_bfloat16* __restrict__ hi,
    __nv_bfloat16* __restrict__ lo, int n4)
{
    int i = blockIdx.x * blockDim.x + threadIdx.x;
    if (i >= n4) return;
    float4 v = ((const float4*)in)[i];
    __nv_bfloat16 h0 = __float2bfloat16(v.x), h1 = __float2bfloat16(v.y);
    __nv_bfloat16 h2 = __float2bfloat16(v.z), h3 = __float2bfloat16(v.w);
    __nv_bfloat16 l0 = __float2bfloat16(v.x - __bfloat162float(h0));
    __nv_bfloat16 l1 = __float2bfloat16(v.y - __bfloat162float(h1));
    __nv_bfloat16 l2 = __float2bfloat16(v.z - __bfloat162float(h2));
    __nv_bfloat16 l3 = __float2bfloat16(v.w - __bfloat162float(h3));
    __nv_bfloat162* hp = (__nv_bfloat162*)hi;
    __nv_bfloat162* lp = (__nv_bfloat162*)lo;
    hp[2*i]   = __nv_bfloat162(h0, h1);
    hp[2*i+1] = __nv_bfloat162(h2, h3);
    lp[2*i]   = __nv_bfloat162(l0, l1);
    lp[2*i+1] = __nv_bfloat162(l2, l3);
}

// ---------------------------------------------------------------------------
// HMMA bf16x3 projection GEMM: out = x @ w^T + bias
// A (x): [8192,1024], B (w): [1024,1024], K-contiguous, hi/lo bf16.
// Tile 128x128 per CTA (grid 8x64 = 512), 8 warps, warp tile 32x64.
// K-chunk 64 bf16 (128B rows, SW128 swizzle), cp.async double buffer.
// Stage layout (64KB): Ah[128][64] | Al | Bh[128][64] | Bl, 16KB each.
// tmode 0: write [b,h,s,d]; tmode 1: write [b,h,d,s].
// ---------------------------------------------------------------------------
__device__ __forceinline__ void proj_issue_stage(
    uint32_t sbase, int stage, int kt,
    const __nv_bfloat16* Ah, const __nv_bfloat16* Al,
    const __nv_bfloat16* Bh, const __nv_bfloat16* Bl,
    int rowBase, int colBase, int tid)
{
    const uint32_t st = sbase + stage * 65536;
    const int k0 = kt * 64;
#pragma unroll
    for (int t = 0; t < 4; t++) {
        const __nv_bfloat16* g = (t == 0) ? Ah : (t == 1) ? Al : (t == 2) ? Bh : Bl;
        const int gr0 = (t < 2) ? rowBase : colBase;
        const uint32_t tb = st + t * 16384;
#pragma unroll
        for (int u = 0; u < 4; u++) {
            int cid = tid + u * 256;        // 0..1023 chunks of 16B
            int row = cid >> 3, c8 = cid & 7;
            uint32_t off = row * 128 + c8 * 16;
            uint32_t sw  = off ^ ((off >> 3) & 0x70);
            const void* gp = g + (size_t)(gr0 + row) * NE + k0 + c8 * 8;
            CP_ASYNC16(tb + sw, gp);
        }
    }
}

__global__ __launch_bounds__(256) void proj_kernel(
    const __nv_bfloat16* __restrict__ Ah, const __nv_bfloat16* __restrict__ Al,
    const __nv_bfloat16* __restrict__ Bh, const __nv_bfloat16* __restrict__ Bl,
    const float* __restrict__ bias, float* __restrict__ out, int tmode)
{
    extern __shared__ char smem[];
    const uint32_t sbase = smem_u32(smem);
    const int tid = threadIdx.x, wid = tid >> 5, lane = tid & 31;
    const int rowBase = blockIdx.y * 128;
    const int colBase = blockIdx.x * 128;
    const int wm = (wid >> 1) * 32;      // warp M offset in tile
    const int wn = (wid & 1) * 64;       // warp N offset in tile

    float c[2][8][4];
#pragma unroll
    for (int i = 0; i < 2; i++)
#pragma unroll
        for (int j = 0; j < 8; j++)
#pragma unroll
            for (int k = 0; k < 4; k++) c[i][j][k] = 0.f;

    proj_issue_stage(sbase, 0, 0, Ah, Al, Bh, Bl, rowBase, colBase, tid);
    CP_COMMIT();
    proj_issue_stage(sbase, 1, 1, Ah, Al, Bh, Bl, rowBase, colBase, tid);
    CP_COMMIT();

    // ldmatrix lane geometry (constant per thread)
    const int agrp = lane >> 3;
    const int arow_off = (lane & 7) + (agrp & 1) * 8;   // within 16-row A tile
    const int akh = (agrp >> 1) * 8;                    // A k-half
    const int brow_off = (lane & 7) + (agrp >> 1) * 8;  // within 16-row B pair
    const int bkh = (agrp & 1) * 8;                     // B k-half

    for (int kt = 0; kt < 16; kt++) {
        CP_WAIT1();
        __syncthreads();
        const uint32_t st = sbase + (kt & 1) * 65536;
        const uint32_t Ah_b = st, Bh_b = st + 32768;

#pragma unroll
        for (int kk = 0; kk < 4; kk++) {
            uint32_t ah[2][4], al[2][4], bh[8][2], bl[8][2];
#pragma unroll
            for (int mt = 0; mt < 2; mt++) {
                int row = wm + mt * 16 + arow_off;
                int k2 = (kk * 16 + akh) * 2;
                uint32_t addr = Ah_b + row * 128 + (k2 ^ ((row & 7) << 4));
                ldm_x4(ah[mt], addr);
                ldm_x4(al[mt], addr + 16384);
            }
#pragma unroll
            for (int p = 0; p < 4; p++) {
                int nrow = wn + p * 16 + brow_off;
                int k2 = (kk * 16 + bkh) * 2;
                uint32_t addr = Bh_b + nrow * 128 + (k2 ^ ((nrow & 7) << 4));
                uint32_t t4[4];
                ldm_x4(t4, addr);
                bh[2*p][0] = t4[0]; bh[2*p][1] = t4[1];
                bh[2*p+1][0] = t4[2]; bh[2*p+1][1] = t4[3];
                ldm_x4(t4, addr + 16384);
                bl[2*p][0] = t4[0]; bl[2*p][1] = t4[1];
                bl[2*p+1][0] = t4[2]; bl[2*p+1][1] = t4[3];
            }
#pragma unroll
            for (int mt = 0; mt < 2; mt++)
#pragma unroll
                for (int nt = 0; nt < 8; nt++) {
                    mma16816(c[mt][nt], ah[mt], bh[nt]);
                    mma16816(c[mt][nt], ah[mt], bl[nt]);
                    mma16816(c[mt][nt], al[mt], bh[nt]);
                }
        }
        __syncthreads();
        if (kt + 2 < 16)
            proj_issue_stage(sbase, kt & 1, kt + 2, Ah, Al, Bh, Bl, rowBase, colBase, tid);
        CP_COMMIT();
    }

    // Epilogue: c[mt][nt] lanes: (row = base + lane/4 [+8], col = base + 2*(lane%4) [+1])
#pragma unroll
    for (int mt = 0; mt < 2; mt++) {
#pragma unroll
        for (int nt = 0; nt < 8; nt++) {
            int r0  = rowBase + wm + mt * 16 + (lane >> 2);
            int col = colBase + wn + nt * 8 + ((lane & 3) << 1);
            float b0 = bias[col], b1 = bias[col + 1];
            int h = col >> 6, d = col & 63;
#pragma unroll
            for (int half = 0; half < 2; half++) {
                int r = r0 + half * 8;
                int bb = r >> 11, s = r & (NS - 1);
                float v0 = c[mt][nt][half*2+0] + b0;
                float v1 = c[mt][nt][half*2+1] + b1;
                if (tmode == 0) {
                    float2* p = (float2*)&out[(((size_t)bb*NH + h)*NS + s)*ND + d];
                    *p = make_float2(v0, v1);
                } else {
                    out[(((size_t)bb*NH + h)*ND + d    )*NS + s] = v0;
                    out[(((size_t)bb*NH + h)*ND + d + 1)*NS + s] = v1;
                }
            }
        }
    }
}

// ---------------------------------------------------------------------------
// Flash attention (causal) — unchanged from R1 (fp32 SIMT).
// ---------------------------------------------------------------------------
__global__ __launch_bounds__(256) void attn_kernel(float* __restrict__ out)
{
    extern __shared__ float sm[];
    float* QsT = sm;
    float* KsT = sm + 64*64;
    float* Vs  = sm + 64*64 + 64*68;

    const int tid = threadIdx.x;
    const int b = blockIdx.z, h = blockIdx.y, qt = blockIdx.x;
    const int tr = tid >> 4, tc = tid & 15;
    const size_t head = ((size_t)b*NH + h) * (size_t)(NS*ND);

    {
        const float* Qg = g_Q + head + qt*64;
#pragma unroll
        for (int u = 0; u < 4; u++) {
            int id = tid + u*256;
            int dd = id >> 4;
            int c4 = (id & 15) << 2;
            float4 q = *(const float4*)&Qg[(size_t)dd*NS + c4];
            q.x *= 0.125f; q.y *= 0.125f; q.z *= 0.125f; q.w *= 0.125f;
            *(float4*)&QsT[dd*64 + c4] = q;
        }
    }

    float mx[4], ls[4], o[4][4];
#pragma unroll
    for (int i = 0; i < 4; i++) {
        mx[i] = -1e30f; ls[i] = 0.f;
#pragma unroll
        for (int j = 0; j < 4; j++) o[i][j] = 0.f;
    }

    const int nt = qt + 1;
    for (int kt = 0; kt < nt; kt++) {
        const float* Kg = g_K + head + kt*64;
        const float* Vg = g_V + head + (size_t)kt*64*ND;
        float4 kreg[4], vreg[4];
#pragma unroll
        for (int u = 0; u < 4; u++) {
            int id = tid + u*256;
            int r  = id >> 4;
            int c4 = (id & 15) << 2;
            kreg[u] = *(const float4*)&Kg[(size_t)r*NS + c4];
            vreg[u] = *(const float4*)&Vg[r*ND + c4];
        }
        __syncthreads();
#pragma unroll
        for (int u = 0; u < 4; u++) {
            int id = tid + u*256;
            int r  = id >> 4;
            int c4 = (id & 15) << 2;
            *(float4*)&KsT[r*68 + c4] = kreg[u];
            *(float4*)&Vs[r*64 + c4]  = vreg[u];
        }
        __syncthreads();

        float acc[4][4] = {};
#pragma unroll 8
        for (int d = 0; d < 64; d++) {
            float4 a4 = *(const float4*)&QsT[d*64 + (tr<<2)];
            float4 b4 = *(const float4*)&KsT[d*68 + (tc<<2)];
            float a[4]  = {a4.x, a4.y, a4.z, a4.w};
            float bq[4] = {b4.x, b4.y, b4.z, b4.w};
#pragma unroll
            for (int i = 0; i < 4; i++)
#pragma unroll
                for (int j = 0; j < 4; j++)
                    acc[i][j] = fmaf(a[i], bq[j], acc[i][j]);
        }

        if (kt == qt) {
#pragma unroll
            for (int i = 0; i < 4; i++)
#pragma unroll
                for (int j = 0; j < 4; j++)
                    if ((tc<<2)+j > (tr<<2)+i) acc[i][j] = -1e30f;
        }

        float sc[4];
#pragma unroll
        for (int i = 0; i < 4; i++) {
            float rm = fmaxf(fmaxf(acc[i][0], acc[i][1]), fmaxf(acc[i][2], acc[i][3]));
            rm = fmaxf(rm, __shfl_xor_sync(0xffffffffu, rm, 1));
            rm = fmaxf(rm, __shfl_xor_sync(0xffffffffu, rm, 2));
            rm = fmaxf(rm, __shfl_xor_sync(0xffffffffu, rm, 4));
            rm = fmaxf(rm, __shfl_xor_sync(0xffffffffu, rm, 8));
            float mn = fmaxf(mx[i], rm);
            sc[i] = __expf(mx[i] - mn);
            mx[i] = mn;
            float rs = 0.f;
#pragma unroll
            for (int j = 0; j < 4; j++) { acc[i][j] = __expf(acc[i][j] - mn); rs += acc[i][j]; }
            rs += __shfl_xor_sync(0xffffffffu, rs, 1);
            rs += __shfl_xor_sync(0xffffffffu, rs, 2);
            rs += __shfl_xor_sync(0xffffffffu, rs, 4);
            rs += __shfl_xor_sync(0xffffffffu, rs, 8);
            ls[i] = ls[i]*sc[i] + rs;
#pragma unroll
            for (int j = 0; j < 4; j++) o[i][j] *= sc[i];
        }

        __syncthreads();
#pragma unroll
        for (int i = 0; i < 4; i++)
            *(float4*)&KsT[((tr<<2)+i)*68 + (tc<<2)] =
                make_float4(acc[i][0], acc[i][1], acc[i][2], acc[i][3]);
        __syncthreads();

#pragma unroll 4
        for (int jj = 0; jj < 64; jj++) {
            float4 v4 = *(const float4*)&Vs[jj*64 + (tc<<2)];
#pragma unroll
            for (int i = 0; i < 4; i++) {
                float pb = KsT[((tr<<2)+i)*68 + jj];
                o[i][0] = fmaf(pb, v4.x, o[i][0]);
                o[i][1] = fmaf(pb, v4.y, o[i][1]);
                o[i][2] = fmaf(pb, v4.z, o[i][2]);
                o[i][3] = fmaf(pb, v4.w, o[i][3]);
            }
        }
    }

#pragma unroll
    for (int i = 0; i < 4; i++) {
        int s = qt*64 + (tr<<2) + i;
        float inv = 1.0f / ls[i];
        float4 r = make_float4(o[i][0]*inv, o[i][1]*inv, o[i][2]*inv, o[i][3]*inv);
        *(float4*)&out[((size_t)b*NS + s)*NN + h*ND + (tc<<2)] = r;
    }
}

// ---------------------------------------------------------------------------
extern "C" void kernel_launch(void* const* d_in, const int* in_sizes, int n_in,
                              void* d_out, int out_size)
{
    (void)in_sizes; (void)n_in; (void)out_size;
    const float* x_q  = (const float*)d_in[0];
    const float* x_kv = (const float*)d_in[1];
    const float* w_q = (const float*)d_in[3];
    const float* b_q = (const float*)d_in[4];
    const float* w_k = (const float*)d_in[5];
    const float* b_k = (const float*)d_in[6];
    const float* w_v = (const float*)d_in[7];
    const float* b_v = (const float*)d_in[8];
    float* out = (float*)d_out;

    float *qp, *kp, *vp;
    cudaGetSymbolAddress((void**)&qp, g_Q);
    cudaGetSymbolAddress((void**)&kp, g_K);
    cudaGetSymbolAddress((void**)&vp, g_V);
    __nv_bfloat16 *xqh, *xql, *xkh, *xkl, *wqh, *wql, *wkh, *wkl, *wvh, *wvl;
    cudaGetSymbolAddress((void**)&xqh, g_xq_h);  cudaGetSymbolAddress((void**)&xql, g_xq_l);
    cudaGetSymbolAddress((void**)&xkh, g_xkv_h); cudaGetSymbolAddress((void**)&xkl, g_xkv_l);
    cudaGetSymbolAddress((void**)&wqh, g_wq_h);  cudaGetSymbolAddress((void**)&wql, g_wq_l);
    cudaGetSymbolAddress((void**)&wkh, g_wk_h);  cudaGetSymbolAddress((void**)&wkl, g_wk_l);
    cudaGetSymbolAddress((void**)&wvh, g_wv_h);  cudaGetSymbolAddress((void**)&wvl, g_wv_l);

    const int nx4 = NM*NE/4, nw4 = NN*NE/4;
    split_kernel<<<(nx4+255)/256, 256>>>(x_q,  xqh, xql, nx4);
    split_kernel<<<(nx4+255)/256, 256>>>(x_kv, xkh, xkl, nx4);
    split_kernel<<<(nw4+255)/256, 256>>>(w_q,  wqh, wql, nw4);
    split_kernel<<<(nw4+255)/256, 256>>>(w_k,  wkh, wkl, nw4);
    split_kernel<<<(nw4+255)/256, 256>>>(w_v,  wvh, wvl, nw4);

    const int psmem = 2 * 65536;   // 131072
    cudaFuncSetAttribute(proj_kernel, cudaFuncAttributeMaxDynamicSharedMemorySize, psmem);
    dim3 pg(NN/128, NM/128);       // (8, 64) = 512 CTAs
    proj_kernel<<<pg, 256, psmem>>>(xqh, xql, wqh, wql, b_q, qp, 1);  // Q -> [b,h,d,s]
    proj_kernel<<<pg, 256, psmem>>>(xkh, xkl, wkh, wkl, b_k, kp, 1);  // K -> [b,h,d,s]
    proj_kernel<<<pg, 256, psmem>>>(xkh, xkl, wvh, wvl, b_v, vp, 0);  // V -> [b,h,s,d]

    const int asmem = (64*64 + 64*68 + 64*64) * (int)sizeof(float);
    cudaFuncSetAttribute(attn_kernel, cudaFuncAttributeMaxDynamicSharedMemorySize, asmem);
    attn_kernel<<<dim3(NS/64, NH, NB), 256, asmem>>>(out);
}

// round 9
// speedup vs baseline: 3.3175x; 1.9766x over previous
#include <cuda_runtime.h>
#include <cuda_bf16.h>
#include <cstdint>

// Problem constants
#define NB 4
#define NS 2048
#define NE 1024
#define NH 16
#define ND 64
#define NM (NB*NS)   // 8192
#define NN (NH*ND)   // 1024

// bf16 hi/lo splits of activations and weights
__device__ __nv_bfloat16 g_xq_h [(size_t)NM*NE], g_xq_l [(size_t)NM*NE];
__device__ __nv_bfloat16 g_xkv_h[(size_t)NM*NE], g_xkv_l[(size_t)NM*NE];
__device__ __nv_bfloat16 g_wq_h [(size_t)NN*NE], g_wq_l [(size_t)NN*NE];
__device__ __nv_bfloat16 g_wk_h [(size_t)NN*NE], g_wk_l [(size_t)NN*NE];
__device__ __nv_bfloat16 g_wv_h [(size_t)NN*NE], g_wv_l [(size_t)NN*NE];

// bf16 hi/lo Q,K ([b,h,s,d], Q pre-scaled by 0.125) and V ([b,h,d,s])
__device__ __nv_bfloat16 g_Qh[(size_t)NB*NH*NS*ND], g_Ql[(size_t)NB*NH*NS*ND];
__device__ __nv_bfloat16 g_Kh[(size_t)NB*NH*NS*ND], g_Kl[(size_t)NB*NH*NS*ND];
__device__ __nv_bfloat16 g_Vh[(size_t)NB*NH*NS*ND], g_Vl[(size_t)NB*NH*NS*ND];

// ---------------------------------------------------------------------------
// Helpers (plain compute_103-legal: cp.async, ldmatrix, mma.sync)
// ---------------------------------------------------------------------------
__device__ __forceinline__ uint32_t smem_u32(const void* p) {
    uint32_t a;
    asm("{ .reg .u64 t; cvta.to.shared.u64 t, %1; cvt.u32.u64 %0, t; }" : "=r"(a) : "l"(p));
    return a;
}
#define CP_ASYNC16(s, g)  asm volatile("cp.async.cg.shared.global [%0], [%1], 16;" :: "r"(s), "l"(g) : "memory")
#define CP_COMMIT()       asm volatile("cp.async.commit_group;" ::: "memory")
#define CP_WAIT1()        asm volatile("cp.async.wait_group 1;" ::: "memory")
#define CP_WAIT0()        asm volatile("cp.async.wait_group 0;" ::: "memory")

__device__ __forceinline__ void ldm_x4(uint32_t* r, uint32_t addr) {
    asm volatile("ldmatrix.sync.aligned.m8n8.x4.shared.b16 {%0,%1,%2,%3}, [%4];"
        : "=r"(r[0]), "=r"(r[1]), "=r"(r[2]), "=r"(r[3]) : "r"(addr));
}
__device__ __forceinline__ void mma16816(float* c, const uint32_t* a, const uint32_t* b) {
    asm volatile("mma.sync.aligned.m16n8k16.row.col.f32.bf16.bf16.f32 "
        "{%0,%1,%2,%3}, {%4,%5,%6,%7}, {%8,%9}, {%0,%1,%2,%3};"
        : "+f"(c[0]), "+f"(c[1]), "+f"(c[2]), "+f"(c[3])
        : "r"(a[0]), "r"(a[1]), "r"(a[2]), "r"(a[3]), "r"(b[0]), "r"(b[1]));
}
// split two floats into packed bf16x2 hi and lo words (low half = first elem)
__device__ __forceinline__ void split2(float a, float b, uint32_t& hi, uint32_t& lo) {
    __nv_bfloat16 ha = __float2bfloat16(a), hb = __float2bfloat16(b);
    __nv_bfloat16 la = __float2bfloat16(a - __bfloat162float(ha));
    __nv_bfloat16 lb = __float2bfloat16(b - __bfloat162float(hb));
    __nv_bfloat162 H(ha, hb), L(la, lb);
    hi = *reinterpret_cast<uint32_t*>(&H);
    lo = *reinterpret_cast<uint32_t*>(&L);
}

// ---------------------------------------------------------------------------
// Split fp32 -> bf16 hi + lo
// ---------------------------------------------------------------------------
__global__ __launch_bounds__(256) void split_kernel(
    const float* __restrict__ in, __nv_bfloat16* __restrict__ hi,
    __nv_bfloat16* __restrict__ lo, int n4)
{
    int i = blockIdx.x * blockDim.x + threadIdx.x;
    if (i >= n4) return;
    float4 v = ((const float4*)in)[i];
    __nv_bfloat16 h0 = __float2bfloat16(v.x), h1 = __float2bfloat16(v.y);
    __nv_bfloat16 h2 = __float2bfloat16(v.z), h3 = __float2bfloat16(v.w);
    __nv_bfloat16 l0 = __float2bfloat16(v.x - __bfloat162float(h0));
    __nv_bfloat16 l1 = __float2bfloat16(v.y - __bfloat162float(h1));
    __nv_bfloat16 l2 = __float2bfloat16(v.z - __bfloat162float(h2));
    __nv_bfloat16 l3 = __float2bfloat16(v.w - __bfloat162float(h3));
    __nv_bfloat162* hp = (__nv_bfloat162*)hi;
    __nv_bfloat162* lp = (__nv_bfloat162*)lo;
    hp[2*i]   = __nv_bfloat162(h0, h1);
    hp[2*i+1] = __nv_bfloat162(h2, h3);
    lp[2*i]   = __nv_bfloat162(l0, l1);
    lp[2*i+1] = __nv_bfloat162(l2, l3);
}

// ---------------------------------------------------------------------------
// HMMA bf16x3 projection GEMM: y = (x @ w^T + bias) * scale -> bf16 hi/lo
// tmode 0: write [b,h,s,d] (d-contiguous). tmode 1: write [b,h,d,s].
// ---------------------------------------------------------------------------
__device__ __forceinline__ void proj_issue_stage(
    uint32_t sbase, int stage, int kt,
    const __nv_bfloat16* Ah, const __nv_bfloat16* Al,
    const __nv_bfloat16* Bh, const __nv_bfloat16* Bl,
    int rowBase, int colBase, int tid)
{
    const uint32_t st = sbase + stage * 65536;
    const int k0 = kt * 64;
#pragma unroll
    for (int t = 0; t < 4; t++) {
        const __nv_bfloat16* g = (t == 0) ? Ah : (t == 1) ? Al : (t == 2) ? Bh : Bl;
        const int gr0 = (t < 2) ? rowBase : colBase;
        const uint32_t tb = st + t * 16384;
#pragma unroll
        for (int u = 0; u < 4; u++) {
            int cid = tid + u * 256;
            int row = cid >> 3, c8 = cid & 7;
            uint32_t off = row * 128 + c8 * 16;
            uint32_t sw  = off ^ ((off >> 3) & 0x70);
            const void* gp = g + (size_t)(gr0 + row) * NE + k0 + c8 * 8;
            CP_ASYNC16(tb + sw, gp);
        }
    }
}

__global__ __launch_bounds__(256) void proj_kernel(
    const __nv_bfloat16* __restrict__ Ah, const __nv_bfloat16* __restrict__ Al,
    const __nv_bfloat16* __restrict__ Bh, const __nv_bfloat16* __restrict__ Bl,
    const float* __restrict__ bias,
    __nv_bfloat16* __restrict__ outH, __nv_bfloat16* __restrict__ outL,
    int tmode, float scale)
{
    extern __shared__ char smem[];
    const uint32_t sbase = smem_u32(smem);
    const int tid = threadIdx.x, wid = tid >> 5, lane = tid & 31;
    const int rowBase = blockIdx.y * 128;
    const int colBase = blockIdx.x * 128;
    const int wm = (wid >> 1) * 32;
    const int wn = (wid & 1) * 64;

    float c[2][8][4];
#pragma unroll
    for (int i = 0; i < 2; i++)
#pragma unroll
        for (int j = 0; j < 8; j++)
#pragma unroll
            for (int k = 0; k < 4; k++) c[i][j][k] = 0.f;

    proj_issue_stage(sbase, 0, 0, Ah, Al, Bh, Bl, rowBase, colBase, tid);
    CP_COMMIT();
    proj_issue_stage(sbase, 1, 1, Ah, Al, Bh, Bl, rowBase, colBase, tid);
    CP_COMMIT();

    const int agrp = lane >> 3;
    const int arow_off = (lane & 7) + (agrp & 1) * 8;
    const int akh = (agrp >> 1) * 8;
    const int brow_off = (lane & 7) + (agrp >> 1) * 8;
    const int bkh = (agrp & 1) * 8;

    for (int kt = 0; kt < 16; kt++) {
        CP_WAIT1();
        __syncthreads();
        const uint32_t st = sbase + (kt & 1) * 65536;
        const uint32_t Ah_b = st, Bh_b = st + 32768;

#pragma unroll
        for (int kk = 0; kk < 4; kk++) {
            uint32_t ah[2][4], al[2][4], bh[8][2], bl[8][2];
#pragma unroll
            for (int mt = 0; mt < 2; mt++) {
                int row = wm + mt * 16 + arow_off;
                int k2 = (kk * 16 + akh) * 2;
                uint32_t addr = Ah_b + row * 128 + (k2 ^ ((row & 7) << 4));
                ldm_x4(ah[mt], addr);
                ldm_x4(al[mt], addr + 16384);
            }
#pragma unroll
            for (int p = 0; p < 4; p++) {
                int nrow = wn + p * 16 + brow_off;
                int k2 = (kk * 16 + bkh) * 2;
                uint32_t addr = Bh_b + nrow * 128 + (k2 ^ ((nrow & 7) << 4));
                uint32_t t4[4];
                ldm_x4(t4, addr);
                bh[2*p][0] = t4[0]; bh[2*p][1] = t4[1];
                bh[2*p+1][0] = t4[2]; bh[2*p+1][1] = t4[3];
                ldm_x4(t4, addr + 16384);
                bl[2*p][0] = t4[0]; bl[2*p][1] = t4[1];
                bl[2*p+1][0] = t4[2]; bl[2*p+1][1] = t4[3];
            }
#pragma unroll
            for (int mt = 0; mt < 2; mt++)
#pragma unroll
                for (int nt = 0; nt < 8; nt++) {
                    mma16816(c[mt][nt], ah[mt], bh[nt]);
                    mma16816(c[mt][nt], ah[mt], bl[nt]);
                    mma16816(c[mt][nt], al[mt], bh[nt]);
                }
        }
        __syncthreads();
        if (kt + 2 < 16)
            proj_issue_stage(sbase, kt & 1, kt + 2, Ah, Al, Bh, Bl, rowBase, colBase, tid);
        CP_COMMIT();
    }

#pragma unroll
    for (int mt = 0; mt < 2; mt++) {
#pragma unroll
        for (int nt = 0; nt < 8; nt++) {
            int r0  = rowBase + wm + mt * 16 + (lane >> 2);
            int col = colBase + wn + nt * 8 + ((lane & 3) << 1);
            float b0 = bias[col], b1 = bias[col + 1];
            int hh = col >> 6, d = col & 63;
#pragma unroll
            for (int half = 0; half < 2; half++) {
                int r = r0 + half * 8;
                int bb = r >> 11, s = r & (NS - 1);
                float v0 = (c[mt][nt][half*2+0] + b0) * scale;
                float v1 = (c[mt][nt][half*2+1] + b1) * scale;
                __nv_bfloat16 h0 = __float2bfloat16(v0), h1 = __float2bfloat16(v1);
                __nv_bfloat16 l0 = __float2bfloat16(v0 - __bfloat162float(h0));
                __nv_bfloat16 l1 = __float2bfloat16(v1 - __bfloat162float(h1));
                if (tmode == 0) {
                    size_t idx = (((size_t)bb*NH + hh)*NS + s)*ND + d;
                    *(__nv_bfloat162*)&outH[idx] = __nv_bfloat162(h0, h1);
                    *(__nv_bfloat162*)&outL[idx] = __nv_bfloat162(l0, l1);
                } else {
                    size_t idx = (((size_t)bb*NH + hh)*ND + d)*NS + s;
                    outH[idx] = h0; outH[idx + NS] = h1;
                    outL[idx] = l0; outL[idx + NS] = l1;
                }
            }
        }
    }
}

// ---------------------------------------------------------------------------
// Tensor-core flash attention (causal). CTA = (b, h, 64-row q-tile), 4 warps.
// Q,K bf16 hi/lo [b,h,s,d] (Q pre-scaled); V bf16 hi/lo [b,h,d,s].
// SMEM: Q hi/lo 16KB + 2 stages x (Kh,Kl,Vh,Vl 8KB each) = 80KB.
// ---------------------------------------------------------------------------
__device__ __forceinline__ void attn_issue_kv(
    uint32_t st, int kt,
    const __nv_bfloat16* Kh, const __nv_bfloat16* Kl,
    const __nv_bfloat16* Vh, const __nv_bfloat16* Vl, int tid)
{
#pragma unroll
    for (int u = 0; u < 16; u++) {
        int cid = tid + u * 128;     // 0..2047
        int t = cid >> 9, r = (cid >> 3) & 63, c8 = cid & 7;
        uint32_t off = r * 128 + c8 * 16;
        uint32_t sw  = off ^ ((off >> 3) & 0x70);
        const __nv_bfloat16* src;
        if (t == 0)      src = Kh + (size_t)(kt*64 + r)*ND + c8*8;
        else if (t == 1) src = Kl + (size_t)(kt*64 + r)*ND + c8*8;
        else if (t == 2) src = Vh + (size_t)r*NS + kt*64 + c8*8;
        else             src = Vl + (size_t)r*NS + kt*64 + c8*8;
        CP_ASYNC16(st + t*8192 + sw, src);
    }
}

__global__ __launch_bounds__(128) void attn_kernel(float* __restrict__ out)
{
    extern __shared__ char smem[];
    const uint32_t sbase = smem_u32(smem);
    const int tid = threadIdx.x, wid = tid >> 5, lane = tid & 31;
    const int b = blockIdx.z, h = blockIdx.y, qt = blockIdx.x;
    const size_t head = ((size_t)b*NH + h) * (size_t)(NS*ND);

    const __nv_bfloat16 *Qhp = g_Qh + head, *Qlp = g_Ql + head;
    const __nv_bfloat16 *Khp = g_Kh + head, *Klp = g_Kl + head;
    const __nv_bfloat16 *Vhp = g_Vh + head, *Vlp = g_Vl + head;

    const uint32_t sQ = sbase;                // Qh 8K | Ql 8K
    const uint32_t sS0 = sbase + 16384;       // stages of 32K

    // Prologue: Q tile + KV stage 0 in one group
#pragma unroll
    for (int u = 0; u < 8; u++) {
        int cid = tid + u * 128;              // 0..1023
        int hf = cid >> 9, r = (cid >> 3) & 63, c8 = cid & 7;
        uint32_t off = r * 128 + c8 * 16;
        uint32_t sw  = off ^ ((off >> 3) & 0x70);
        const __nv_bfloat16* src = (hf ? Qlp : Qhp) + (size_t)(qt*64 + r)*ND + c8*8;
        CP_ASYNC16(sQ + hf*8192 + sw, src);
    }
    attn_issue_kv(sS0, 0, Khp, Klp, Vhp, Vlp, tid);
    CP_COMMIT();

    const int agrp = lane >> 3;
    const int arow = (lane & 7) + (agrp & 1) * 8;
    const int akh  = (agrp >> 1) * 8;
    const int brow = (lane & 7) + (agrp >> 1) * 8;
    const int bkh  = (agrp & 1) * 8;
    const int wm = wid * 16;

    float m0 = -1e30f, m1 = -1e30f, l0 = 0.f, l1 = 0.f;
    float co[8][4];
#pragma unroll
    for (int i = 0; i < 8; i++)
#pragma unroll
        for (int j = 0; j < 4; j++) co[i][j] = 0.f;
    uint32_t qh[4][4], ql[4][4];

    for (int kt = 0; kt <= qt; kt++) {
        if (kt < qt) {
            attn_issue_kv(sS0 + ((kt+1)&1)*32768, kt+1, Khp, Klp, Vhp, Vlp, tid);
            CP_COMMIT();
            CP_WAIT1();
        } else {
            CP_WAIT0();
        }
        __syncthreads();
        const uint32_t st = sS0 + (kt & 1) * 32768;

        if (kt == 0) {
#pragma unroll
            for (int kk = 0; kk < 4; kk++) {
                int row = wm + arow;
                uint32_t a = sQ + row * 128 + (((kk*16 + akh)*2) ^ ((row & 7) << 4));
                ldm_x4(qh[kk], a);
                ldm_x4(ql[kk], a + 8192);
            }
        }

        // S = Q K^T (3-term)
        float sa[8][4];
#pragma unroll
        for (int i = 0; i < 8; i++)
#pragma unroll
            for (int j = 0; j < 4; j++) sa[i][j] = 0.f;
#pragma unroll
        for (int kk = 0; kk < 4; kk++) {
            uint32_t bh_[8][2], bl_[8][2], t4[4];
#pragma unroll
            for (int p = 0; p < 4; p++) {
                int nr = p * 16 + brow;
                uint32_t a = st + nr * 128 + (((kk*16 + bkh)*2) ^ ((nr & 7) << 4));
                ldm_x4(t4, a);
                bh_[2*p][0] = t4[0]; bh_[2*p][1] = t4[1];
                bh_[2*p+1][0] = t4[2]; bh_[2*p+1][1] = t4[3];
                ldm_x4(t4, a + 8192);
                bl_[2*p][0] = t4[0]; bl_[2*p][1] = t4[1];
                bl_[2*p+1][0] = t4[2]; bl_[2*p+1][1] = t4[3];
            }
#pragma unroll
            for (int nt = 0; nt < 8; nt++) {
                mma16816(sa[nt], qh[kk], bh_[nt]);
                mma16816(sa[nt], qh[kk], bl_[nt]);
                mma16816(sa[nt], ql[kk], bh_[nt]);
            }
        }

        // Causal mask (diagonal tile only)
        if (kt == qt) {
            int r0 = wm + (lane >> 2);
            int c0b = (lane & 3) << 1;
#pragma unroll
            for (int nt = 0; nt < 8; nt++) {
                int cc = nt * 8 + c0b;
                if (cc     > r0)     sa[nt][0] = -1e30f;
                if (cc + 1 > r0)     sa[nt][1] = -1e30f;
                if (cc     > r0 + 8) sa[nt][2] = -1e30f;
                if (cc + 1 > r0 + 8) sa[nt][3] = -1e30f;
            }
        }

        // Online softmax (rows r and r+8; lanes sharing a row differ in lane&3)
        float rm0 = -1e30f, rm1 = -1e30f;
#pragma unroll
        for (int nt = 0; nt < 8; nt++) {
            rm0 = fmaxf(rm0, fmaxf(sa[nt][0], sa[nt][1]));
            rm1 = fmaxf(rm1, fmaxf(sa[nt][2], sa[nt][3]));
        }
        rm0 = fmaxf(rm0, __shfl_xor_sync(0xffffffffu, rm0, 1));
        rm0 = fmaxf(rm0, __shfl_xor_sync(0xffffffffu, rm0, 2));
        rm1 = fmaxf(rm1, __shfl_xor_sync(0xffffffffu, rm1, 1));
        rm1 = fmaxf(rm1, __shfl_xor_sync(0xffffffffu, rm1, 2));
        float mn0 = fmaxf(m0, rm0), mn1 = fmaxf(m1, rm1);
        float sc0 = __expf(m0 - mn0), sc1 = __expf(m1 - mn1);
        m0 = mn0; m1 = mn1;
        float rs0 = 0.f, rs1 = 0.f;
#pragma unroll
        for (int nt = 0; nt < 8; nt++) {
            sa[nt][0] = __expf(sa[nt][0] - m0); rs0 += sa[nt][0];
            sa[nt][1] = __expf(sa[nt][1] - m0); rs0 += sa[nt][1];
            sa[nt][2] = __expf(sa[nt][2] - m1); rs1 += sa[nt][2];
            sa[nt][3] = __expf(sa[nt][3] - m1); rs1 += sa[nt][3];
        }
        rs0 += __shfl_xor_sync(0xffffffffu, rs0, 1);
        rs0 += __shfl_xor_sync(0xffffffffu, rs0, 2);
        rs1 += __shfl_xor_sync(0xffffffffu, rs1, 1);
        rs1 += __shfl_xor_sync(0xffffffffu, rs1, 2);
        l0 = l0 * sc0 + rs0;
        l1 = l1 * sc1 + rs1;
#pragma unroll
        for (int nt = 0; nt < 8; nt++) {
            co[nt][0] *= sc0; co[nt][1] *= sc0;
            co[nt][2] *= sc1; co[nt][3] *= sc1;
        }

        // O += P V  (P hi/lo packed in registers; V from smem)
#pragma unroll
        for (int kkv = 0; kkv < 4; kkv++) {
            uint32_t pah[4], pal[4];
            split2(sa[2*kkv][0],   sa[2*kkv][1],   pah[0], pal[0]);
            split2(sa[2*kkv][2],   sa[2*kkv][3],   pah[1], pal[1]);
            split2(sa[2*kkv+1][0], sa[2*kkv+1][1], pah[2], pal[2]);
            split2(sa[2*kkv+1][2], sa[2*kkv+1][3], pah[3], pal[3]);
            uint32_t vh_[8][2], vl_[8][2], t4[4];
#pragma unroll
            for (int p = 0; p < 4; p++) {
                int nr = p * 16 + brow;
                uint32_t a = st + 16384 + nr * 128 + (((kkv*16 + bkh)*2) ^ ((nr & 7) << 4));
                ldm_x4(t4, a);
                vh_[2*p][0] = t4[0]; vh_[2*p][1] = t4[1];
                vh_[2*p+1][0] = t4[2]; vh_[2*p+1][1] = t4[3];
                ldm_x4(t4, a + 8192);
                vl_[2*p][0] = t4[0]; vl_[2*p][1] = t4[1];
                vl_[2*p+1][0] = t4[2]; vl_[2*p+1][1] = t4[3];
            }
#pragma unroll
            for (int nv = 0; nv < 8; nv++) {
                mma16816(co[nv], pah, vh_[nv]);
                mma16816(co[nv], pah, vl_[nv]);
                mma16816(co[nv], pal, vh_[nv]);
            }
        }
        __syncthreads();
    }

    // Epilogue: out[b, s, h*64+d] = O / l
    float inv0 = 1.0f / l0, inv1 = 1.0f / l1;
    int s0 = qt * 64 + wm + (lane >> 2);
#pragma unroll
    for (int nv = 0; nv < 8; nv++) {
        int d = nv * 8 + ((lane & 3) << 1);
        float2* p0 = (float2*)&out[((size_t)b*NS + s0)*NN + h*ND + d];
        *p0 = make_float2(co[nv][0]*inv0, co[nv][1]*inv0);
        float2* p1 = (float2*)&out[((size_t)b*NS + s0 + 8)*NN + h*ND + d];
        *p1 = make_float2(co[nv][2]*inv1, co[nv][3]*inv1);
    }
}

// ---------------------------------------------------------------------------
extern "C" void kernel_launch(void* const* d_in, const int* in_sizes, int n_in,
                              void* d_out, int out_size)
{
    (void)in_sizes; (void)n_in; (void)out_size;
    const float* x_q  = (const float*)d_in[0];
    const float* x_kv = (const float*)d_in[1];
    const float* w_q = (const float*)d_in[3];
    const float* b_q = (const float*)d_in[4];
    const float* w_k = (const float*)d_in[5];
    const float* b_k = (const float*)d_in[6];
    const float* w_v = (const float*)d_in[7];
    const float* b_v = (const float*)d_in[8];
    float* out = (float*)d_out;

    __nv_bfloat16 *xqh, *xql, *xkh, *xkl, *wqh, *wql, *wkh, *wkl, *wvh, *wvl;
    cudaGetSymbolAddress((void**)&xqh, g_xq_h);  cudaGetSymbolAddress((void**)&xql, g_xq_l);
    cudaGetSymbolAddress((void**)&xkh, g_xkv_h); cudaGetSymbolAddress((void**)&xkl, g_xkv_l);
    cudaGetSymbolAddress((void**)&wqh, g_wq_h);  cudaGetSymbolAddress((void**)&wql, g_wq_l);
    cudaGetSymbolAddress((void**)&wkh, g_wk_h);  cudaGetSymbolAddress((void**)&wkl, g_wk_l);
    cudaGetSymbolAddress((void**)&wvh, g_wv_h);  cudaGetSymbolAddress((void**)&wvl, g_wv_l);
    __nv_bfloat16 *qH, *qL, *kH, *kL, *vH, *vL;
    cudaGetSymbolAddress((void**)&qH, g_Qh); cudaGetSymbolAddress((void**)&qL, g_Ql);
    cudaGetSymbolAddress((void**)&kH, g_Kh); cudaGetSymbolAddress((void**)&kL, g_Kl);
    cudaGetSymbolAddress((void**)&vH, g_Vh); cudaGetSymbolAddress((void**)&vL, g_Vl);

    const int nx4 = NM*NE/4, nw4 = NN*NE/4;
    split_kernel<<<(nx4+255)/256, 256>>>(x_q,  xqh, xql, nx4);
    split_kernel<<<(nx4+255)/256, 256>>>(x_kv, xkh, xkl, nx4);
    split_kernel<<<(nw4+255)/256, 256>>>(w_q,  wqh, wql, nw4);
    split_kernel<<<(nw4+255)/256, 256>>>(w_k,  wkh, wkl, nw4);
    split_kernel<<<(nw4+255)/256, 256>>>(w_v,  wvh, wvl, nw4);

    const int psmem = 2 * 65536;
    cudaFuncSetAttribute(proj_kernel, cudaFuncAttributeMaxDynamicSharedMemorySize, psmem);
    dim3 pg(NN/128, NM/128);
    proj_kernel<<<pg, 256, psmem>>>(xqh, xql, wqh, wql, b_q, qH, qL, 0, 0.125f);
    proj_kernel<<<pg, 256, psmem>>>(xkh, xkl, wkh, wkl, b_k, kH, kL, 0, 1.0f);
    proj_kernel<<<pg, 256, psmem>>>(xkh, xkl, wvh, wvl, b_v, vH, vL, 1, 1.0f);

    const int asmem = 16384 + 2*32768;   // 81920
    cudaFuncSetAttribute(attn_kernel, cudaFuncAttributeMaxDynamicSharedMemorySize, asmem);
    attn_kernel<<<dim3(NS/64, NH, NB), 128, asmem>>>(out);
}

// round 13
// speedup vs baseline: 3.4844x; 1.0503x over previous
#include <cuda_runtime.h>
#include <cuda_bf16.h>
#include <cstdint>

// Problem constants
#define NB 4
#define NS 2048
#define NE 1024
#define NH 16
#define ND 64
#define NM (NB*NS)   // 8192
#define NN (NH*ND)   // 1024

// bf16 hi/lo splits of activations and weights
__device__ __nv_bfloat16 g_xq_h [(size_t)NM*NE], g_xq_l [(size_t)NM*NE];
__device__ __nv_bfloat16 g_xkv_h[(size_t)NM*NE], g_xkv_l[(size_t)NM*NE];
__device__ __nv_bfloat16 g_wq_h [(size_t)NN*NE], g_wq_l [(size_t)NN*NE];
__device__ __nv_bfloat16 g_wk_h [(size_t)NN*NE], g_wk_l [(size_t)NN*NE];
__device__ __nv_bfloat16 g_wv_h [(size_t)NN*NE], g_wv_l [(size_t)NN*NE];

// bf16 hi/lo Q,K ([b,h,s,d], Q pre-scaled by 0.125) and V ([b,h,d,s])
__device__ __nv_bfloat16 g_Qh[(size_t)NB*NH*NS*ND], g_Ql[(size_t)NB*NH*NS*ND];
__device__ __nv_bfloat16 g_Kh[(size_t)NB*NH*NS*ND], g_Kl[(size_t)NB*NH*NS*ND];
__device__ __nv_bfloat16 g_Vh[(size_t)NB*NH*NS*ND], g_Vl[(size_t)NB*NH*NS*ND];

// ---------------------------------------------------------------------------
// Helpers (plain compute_103-legal: cp.async, ldmatrix, mma.sync)
// ---------------------------------------------------------------------------
__device__ __forceinline__ uint32_t smem_u32(const void* p) {
    uint32_t a;
    asm("{ .reg .u64 t; cvta.to.shared.u64 t, %1; cvt.u32.u64 %0, t; }" : "=r"(a) : "l"(p));
    return a;
}
#define CP_ASYNC16(s, g)  asm volatile("cp.async.cg.shared.global [%0], [%1], 16;" :: "r"(s), "l"(g) : "memory")
#define CP_COMMIT()       asm volatile("cp.async.commit_group;" ::: "memory")
#define CP_WAIT1()        asm volatile("cp.async.wait_group 1;" ::: "memory")
#define CP_WAIT0()        asm volatile("cp.async.wait_group 0;" ::: "memory")

__device__ __forceinline__ void ldm_x4(uint32_t* r, uint32_t addr) {
    asm volatile("ldmatrix.sync.aligned.m8n8.x4.shared.b16 {%0,%1,%2,%3}, [%4];"
        : "=r"(r[0]), "=r"(r[1]), "=r"(r[2]), "=r"(r[3]) : "r"(addr));
}
__device__ __forceinline__ void mma16816(float* c, const uint32_t* a, const uint32_t* b) {
    asm volatile("mma.sync.aligned.m16n8k16.row.col.f32.bf16.bf16.f32 "
        "{%0,%1,%2,%3}, {%4,%5,%6,%7}, {%8,%9}, {%0,%1,%2,%3};"
        : "+f"(c[0]), "+f"(c[1]), "+f"(c[2]), "+f"(c[3])
        : "r"(a[0]), "r"(a[1]), "r"(a[2]), "r"(a[3]), "r"(b[0]), "r"(b[1]));
}
// split two floats into packed bf16x2 hi and lo words (low half = first elem)
__device__ __forceinline__ void split2(float a, float b, uint32_t& hi, uint32_t& lo) {
    __nv_bfloat16 ha = __float2bfloat16(a), hb = __float2bfloat16(b);
    __nv_bfloat16 la = __float2bfloat16(a - __bfloat162float(ha));
    __nv_bfloat16 lb = __float2bfloat16(b - __bfloat162float(hb));
    __nv_bfloat162 H(ha, hb), L(la, lb);
    hi = *reinterpret_cast<uint32_t*>(&H);
    lo = *reinterpret_cast<uint32_t*>(&L);
}

// ---------------------------------------------------------------------------
// Split fp32 -> bf16 hi + lo
// ---------------------------------------------------------------------------
__global__ __launch_bounds__(256) void split_kernel(
    const float* __restrict__ in, __nv_bfloat16* __restrict__ hi,
    __nv_bfloat16* __restrict__ lo, int n4)
{
    int i = blockIdx.x * blockDim.x + threadIdx.x;
    if (i >= n4) return;
    float4 v = ((const float4*)in)[i];
    __nv_bfloat16 h0 = __float2bfloat16(v.x), h1 = __float2bfloat16(v.y);
    __nv_bfloat16 h2 = __float2bfloat16(v.z), h3 = __float2bfloat16(v.w);
    __nv_bfloat16 l0 = __float2bfloat16(v.x - __bfloat162float(h0));
    __nv_bfloat16 l1 = __float2bfloat16(v.y - __bfloat162float(h1));
    __nv_bfloat16 l2 = __float2bfloat16(v.z - __bfloat162float(h2));
    __nv_bfloat16 l3 = __float2bfloat16(v.w - __bfloat162float(h3));
    __nv_bfloat162* hp = (__nv_bfloat162*)hi;
    __nv_bfloat162* lp = (__nv_bfloat162*)lo;
    hp[2*i]   = __nv_bfloat162(h0, h1);
    hp[2*i+1] = __nv_bfloat162(h2, h3);
    lp[2*i]   = __nv_bfloat162(l0, l1);
    lp[2*i+1] = __nv_bfloat162(l2, l3);
}

// ---------------------------------------------------------------------------
// Fused HMMA bf16x3 projection GEMM: z in {0,1,2} selects Q/K/V projection.
// y = (x @ w^T + bias) * scale -> bf16 hi/lo
// tmode 0: write [b,h,s,d] (d-contiguous). tmode 1: write [b,h,d,s].
// ---------------------------------------------------------------------------
__device__ __forceinline__ void proj_issue_stage(
    uint32_t sbase, int stage, int kt,
    const __nv_bfloat16* Ah, const __nv_bfloat16* Al,
    const __nv_bfloat16* Bh, const __nv_bfloat16* Bl,
    int rowBase, int colBase, int tid)
{
    const uint32_t st = sbase + stage * 65536;
    const int k0 = kt * 64;
#pragma unroll
    for (int t = 0; t < 4; t++) {
        const __nv_bfloat16* g = (t == 0) ? Ah : (t == 1) ? Al : (t == 2) ? Bh : Bl;
        const int gr0 = (t < 2) ? rowBase : colBase;
        const uint32_t tb = st + t * 16384;
#pragma unroll
        for (int u = 0; u < 4; u++) {
            int cid = tid + u * 256;
            int row = cid >> 3, c8 = cid & 7;
            uint32_t off = row * 128 + c8 * 16;
            uint32_t sw  = off ^ ((off >> 3) & 0x70);
            const void* gp = g + (size_t)(gr0 + row) * NE + k0 + c8 * 8;
            CP_ASYNC16(tb + sw, gp);
        }
    }
}

__global__ __launch_bounds__(256) void proj_kernel(
    const __nv_bfloat16* __restrict__ xqh, const __nv_bfloat16* __restrict__ xql,
    const __nv_bfloat16* __restrict__ xkh, const __nv_bfloat16* __restrict__ xkl,
    const __nv_bfloat16* __restrict__ wqh, const __nv_bfloat16* __restrict__ wql,
    const __nv_bfloat16* __restrict__ wkh, const __nv_bfloat16* __restrict__ wkl,
    const __nv_bfloat16* __restrict__ wvh, const __nv_bfloat16* __restrict__ wvl,
    const float* __restrict__ bq, const float* __restrict__ bk, const float* __restrict__ bv,
    __nv_bfloat16* __restrict__ qH, __nv_bfloat16* __restrict__ qL,
    __nv_bfloat16* __restrict__ kH, __nv_bfloat16* __restrict__ kL,
    __nv_bfloat16* __restrict__ vH, __nv_bfloat16* __restrict__ vL)
{
    extern __shared__ char smem[];
    const uint32_t sbase = smem_u32(smem);
    const int tid = threadIdx.x, wid = tid >> 5, lane = tid & 31;
    const int z = blockIdx.z;
    const int rowBase = blockIdx.y * 128;
    const int colBase = blockIdx.x * 128;
    const int wm = (wid >> 1) * 32;
    const int wn = (wid & 1) * 64;

    const __nv_bfloat16* Ah = (z == 0) ? xqh : xkh;
    const __nv_bfloat16* Al = (z == 0) ? xql : xkl;
    const __nv_bfloat16* Bh = (z == 0) ? wqh : (z == 1) ? wkh : wvh;
    const __nv_bfloat16* Bl = (z == 0) ? wql : (z == 1) ? wkl : wvl;
    const float* bias = (z == 0) ? bq : (z == 1) ? bk : bv;
    __nv_bfloat16* outH = (z == 0) ? qH : (z == 1) ? kH : vH;
    __nv_bfloat16* outL = (z == 0) ? qL : (z == 1) ? kL : vL;
    const int tmode = (z == 2) ? 1 : 0;
    const float scale = (z == 0) ? 0.125f : 1.0f;

    float c[2][8][4];
#pragma unroll
    for (int i = 0; i < 2; i++)
#pragma unroll
        for (int j = 0; j < 8; j++)
#pragma unroll
            for (int k = 0; k < 4; k++) c[i][j][k] = 0.f;

    proj_issue_stage(sbase, 0, 0, Ah, Al, Bh, Bl, rowBase, colBase, tid);
    CP_COMMIT();
    proj_issue_stage(sbase, 1, 1, Ah, Al, Bh, Bl, rowBase, colBase, tid);
    CP_COMMIT();

    const int agrp = lane >> 3;
    const int arow_off = (lane & 7) + (agrp & 1) * 8;
    const int akh = (agrp >> 1) * 8;
    const int brow_off = (lane & 7) + (agrp >> 1) * 8;
    const int bkh = (agrp & 1) * 8;

    for (int kt = 0; kt < 16; kt++) {
        CP_WAIT1();
        __syncthreads();
        const uint32_t st = sbase + (kt & 1) * 65536;
        const uint32_t Ah_b = st, Bh_b = st + 32768;

#pragma unroll
        for (int kk = 0; kk < 4; kk++) {
            uint32_t ah[2][4], al[2][4], bh[8][2], bl[8][2];
#pragma unroll
            for (int mt = 0; mt < 2; mt++) {
                int row = wm + mt * 16 + arow_off;
                int k2 = (kk * 16 + akh) * 2;
                uint32_t addr = Ah_b + row * 128 + (k2 ^ ((row & 7) << 4));
                ldm_x4(ah[mt], addr);
                ldm_x4(al[mt], addr + 16384);
            }
#pragma unroll
            for (int p = 0; p < 4; p++) {
                int nrow = wn + p * 16 + brow_off;
                int k2 = (kk * 16 + bkh) * 2;
                uint32_t addr = Bh_b + nrow * 128 + (k2 ^ ((nrow & 7) << 4));
                uint32_t t4[4];
                ldm_x4(t4, addr);
                bh[2*p][0] = t4[0]; bh[2*p][1] = t4[1];
                bh[2*p+1][0] = t4[2]; bh[2*p+1][1] = t4[3];
                ldm_x4(t4, addr + 16384);
                bl[2*p][0] = t4[0]; bl[2*p][1] = t4[1];
                bl[2*p+1][0] = t4[2]; bl[2*p+1][1] = t4[3];
            }
#pragma unroll
            for (int mt = 0; mt < 2; mt++)
#pragma unroll
                for (int nt = 0; nt < 8; nt++) {
                    mma16816(c[mt][nt], ah[mt], bh[nt]);
                    mma16816(c[mt][nt], ah[mt], bl[nt]);
                    mma16816(c[mt][nt], al[mt], bh[nt]);
                }
        }
        __syncthreads();
        if (kt + 2 < 16)
            proj_issue_stage(sbase, kt & 1, kt + 2, Ah, Al, Bh, Bl, rowBase, colBase, tid);
        CP_COMMIT();
    }

#pragma unroll
    for (int mt = 0; mt < 2; mt++) {
#pragma unroll
        for (int nt = 0; nt < 8; nt++) {
            int r0  = rowBase + wm + mt * 16 + (lane >> 2);
            int col = colBase + wn + nt * 8 + ((lane & 3) << 1);
            float b0 = bias[col], b1 = bias[col + 1];
            int hh = col >> 6, d = col & 63;
#pragma unroll
            for (int half = 0; half < 2; half++) {
                int r = r0 + half * 8;
                int bb = r >> 11, s = r & (NS - 1);
                float v0 = (c[mt][nt][half*2+0] + b0) * scale;
                float v1 = (c[mt][nt][half*2+1] + b1) * scale;
                __nv_bfloat16 h0 = __float2bfloat16(v0), h1 = __float2bfloat16(v1);
                __nv_bfloat16 l0 = __float2bfloat16(v0 - __bfloat162float(h0));
                __nv_bfloat16 l1 = __float2bfloat16(v1 - __bfloat162float(h1));
                if (tmode == 0) {
                    size_t idx = (((size_t)bb*NH + hh)*NS + s)*ND + d;
                    *(__nv_bfloat162*)&outH[idx] = __nv_bfloat162(h0, h1);
                    *(__nv_bfloat162*)&outL[idx] = __nv_bfloat162(l0, l1);
                } else {
                    size_t idx = (((size_t)bb*NH + hh)*ND + d)*NS + s;
                    outH[idx] = h0; outH[idx + NS] = h1;
                    outL[idx] = l0; outL[idx + NS] = l1;
                }
            }
        }
    }
}

// ---------------------------------------------------------------------------
// Tensor-core flash attention (causal). CTA = (b, h, 64-row q-tile), 4 warps.
// qt reversed (heavy tiles first) for LPT wave scheduling.
// Q,K bf16 hi/lo [b,h,s,d] (Q pre-scaled); V bf16 hi/lo [b,h,d,s].
// SMEM: Q hi/lo 16KB + 2 stages x (Kh,Kl,Vh,Vl 8KB each) = 80KB.
// ---------------------------------------------------------------------------
__device__ __forceinline__ void attn_issue_kv(
    uint32_t st, int kt,
    const __nv_bfloat16* Kh, const __nv_bfloat16* Kl,
    const __nv_bfloat16* Vh, const __nv_bfloat16* Vl, int tid)
{
#pragma unroll
    for (int u = 0; u < 16; u++) {
        int cid = tid + u * 128;     // 0..2047
        int t = cid >> 9, r = (cid >> 3) & 63, c8 = cid & 7;
        uint32_t off = r * 128 + c8 * 16;
        uint32_t sw  = off ^ ((off >> 3) & 0x70);
        const __nv_bfloat16* src;
        if (t == 0)      src = Kh + (size_t)(kt*64 + r)*ND + c8*8;
        else if (t == 1) src = Kl + (size_t)(kt*64 + r)*ND + c8*8;
        else if (t == 2) src = Vh + (size_t)r*NS + kt*64 + c8*8;
        else             src = Vl + (size_t)r*NS + kt*64 + c8*8;
        CP_ASYNC16(st + t*8192 + sw, src);
    }
}

__global__ __launch_bounds__(128) void attn_kernel(float* __restrict__ out)
{
    extern __shared__ char smem[];
    const uint32_t sbase = smem_u32(smem);
    const int tid = threadIdx.x, wid = tid >> 5, lane = tid & 31;
    const int b = blockIdx.z, h = blockIdx.y;
    const int qt = gridDim.x - 1 - blockIdx.x;   // heavy tiles scheduled first
    const size_t head = ((size_t)b*NH + h) * (size_t)(NS*ND);

    const __nv_bfloat16 *Qhp = g_Qh + head, *Qlp = g_Ql + head;
    const __nv_bfloat16 *Khp = g_Kh + head, *Klp = g_Kl + head;
    const __nv_bfloat16 *Vhp = g_Vh + head, *Vlp = g_Vl + head;

    const uint32_t sQ = sbase;                // Qh 8K | Ql 8K
    const uint32_t sS0 = sbase + 16384;       // stages of 32K

    // Prologue: Q tile + KV stage 0 in one group
#pragma unroll
    for (int u = 0; u < 8; u++) {
        int cid = tid + u * 128;              // 0..1023
        int hf = cid >> 9, r = (cid >> 3) & 63, c8 = cid & 7;
        uint32_t off = r * 128 + c8 * 16;
        uint32_t sw  = off ^ ((off >> 3) & 0x70);
        const __nv_bfloat16* src = (hf ? Qlp : Qhp) + (size_t)(qt*64 + r)*ND + c8*8;
        CP_ASYNC16(sQ + hf*8192 + sw, src);
    }
    attn_issue_kv(sS0, 0, Khp, Klp, Vhp, Vlp, tid);
    CP_COMMIT();

    const int agrp = lane >> 3;
    const int arow = (lane & 7) + (agrp & 1) * 8;
    const int akh  = (agrp >> 1) * 8;
    const int brow = (lane & 7) + (agrp >> 1) * 8;
    const int bkh  = (agrp & 1) * 8;
    const int wm = wid * 16;

    float m0 = -1e30f, m1 = -1e30f, l0 = 0.f, l1 = 0.f;
    float co[8][4];
#pragma unroll
    for (int i = 0; i < 8; i++)
#pragma unroll
        for (int j = 0; j < 4; j++) co[i][j] = 0.f;
    uint32_t qh[4][4], ql[4][4];

    for (int kt = 0; kt <= qt; kt++) {
        if (kt < qt) {
            attn_issue_kv(sS0 + ((kt+1)&1)*32768, kt+1, Khp, Klp, Vhp, Vlp, tid);
            CP_COMMIT();
            CP_WAIT1();
        } else {
            CP_WAIT0();
        }
        __syncthreads();
        const uint32_t st = sS0 + (kt & 1) * 32768;

        if (kt == 0) {
#pragma unroll
            for (int kk = 0; kk < 4; kk++) {
                int row = wm + arow;
                uint32_t a = sQ + row * 128 + (((kk*16 + akh)*2) ^ ((row & 7) << 4));
                ldm_x4(qh[kk], a);
                ldm_x4(ql[kk], a + 8192);
            }
        }

        // S = Q K^T (3-term)
        float sa[8][4];
#pragma unroll
        for (int i = 0; i < 8; i++)
#pragma unroll
            for (int j = 0; j < 4; j++) sa[i][j] = 0.f;
#pragma unroll
        for (int kk = 0; kk < 4; kk++) {
            uint32_t bh_[8][2], bl_[8][2], t4[4];
#pragma unroll
            for (int p = 0; p < 4; p++) {
                int nr = p * 16 + brow;
                uint32_t a = st + nr * 128 + (((kk*16 + bkh)*2) ^ ((nr & 7) << 4));
                ldm_x4(t4, a);
                bh_[2*p][0] = t4[0]; bh_[2*p][1] = t4[1];
                bh_[2*p+1][0] = t4[2]; bh_[2*p+1][1] = t4[3];
                ldm_x4(t4, a + 8192);
                bl_[2*p][0] = t4[0]; bl_[2*p][1] = t4[1];
                bl_[2*p+1][0] = t4[2]; bl_[2*p+1][1] = t4[3];
            }
#pragma unroll
            for (int nt = 0; nt < 8; nt++) {
                mma16816(sa[nt], qh[kk], bh_[nt]);
                mma16816(sa[nt], qh[kk], bl_[nt]);
                mma16816(sa[nt], ql[kk], bh_[nt]);
            }
        }

        // Causal mask (diagonal tile only)
        if (kt == qt) {
            int r0 = wm + (lane >> 2);
            int c0b = (lane & 3) << 1;
#pragma unroll
            for (int nt = 0; nt < 8; nt++) {
                int cc = nt * 8 + c0b;
                if (cc     > r0)     sa[nt][0] = -1e30f;
                if (cc + 1 > r0)     sa[nt][1] = -1e30f;
                if (cc     > r0 + 8) sa[nt][2] = -1e30f;
                if (cc + 1 > r0 + 8) sa[nt][3] = -1e30f;
            }
        }

        // Online softmax (rows r and r+8; lanes sharing a row differ in lane&3)
        float rm0 = -1e30f, rm1 = -1e30f;
#pragma unroll
        for (int nt = 0; nt < 8; nt++) {
            rm0 = fmaxf(rm0, fmaxf(sa[nt][0], sa[nt][1]));
            rm1 = fmaxf(rm1, fmaxf(sa[nt][2], sa[nt][3]));
        }
        rm0 = fmaxf(rm0, __shfl_xor_sync(0xffffffffu, rm0, 1));
        rm0 = fmaxf(rm0, __shfl_xor_sync(0xffffffffu, rm0, 2));
        rm1 = fmaxf(rm1, __shfl_xor_sync(0xffffffffu, rm1, 1));
        rm1 = fmaxf(rm1, __shfl_xor_sync(0xffffffffu, rm1, 2));
        float mn0 = fmaxf(m0, rm0), mn1 = fmaxf(m1, rm1);
        float sc0 = __expf(m0 - mn0), sc1 = __expf(m1 - mn1);
        m0 = mn0; m1 = mn1;
        float rs0 = 0.f, rs1 = 0.f;
#pragma unroll
        for (int nt = 0; nt < 8; nt++) {
            sa[nt][0] = __expf(sa[nt][0] - m0); rs0 += sa[nt][0];
            sa[nt][1] = __expf(sa[nt][1] - m0); rs0 += sa[nt][1];
            sa[nt][2] = __expf(sa[nt][2] - m1); rs1 += sa[nt][2];
            sa[nt][3] = __expf(sa[nt][3] - m1); rs1 += sa[nt][3];
        }
        rs0 += __shfl_xor_sync(0xffffffffu, rs0, 1);
        rs0 += __shfl_xor_sync(0xffffffffu, rs0, 2);
        rs1 += __shfl_xor_sync(0xffffffffu, rs1, 1);
        rs1 += __shfl_xor_sync(0xffffffffu, rs1, 2);
        l0 = l0 * sc0 + rs0;
        l1 = l1 * sc1 + rs1;
#pragma unroll
        for (int nt = 0; nt < 8; nt++) {
            co[nt][0] *= sc0; co[nt][1] *= sc0;
            co[nt][2] *= sc1; co[nt][3] *= sc1;
        }

        // O += P V  (P hi/lo packed in registers; V from smem)
#pragma unroll
        for (int kkv = 0; kkv < 4; kkv++) {
            uint32_t pah[4], pal[4];
            split2(sa[2*kkv][0],   sa[2*kkv][1],   pah[0], pal[0]);
            split2(sa[2*kkv][2],   sa[2*kkv][3],   pah[1], pal[1]);
            split2(sa[2*kkv+1][0], sa[2*kkv+1][1], pah[2], pal[2]);
            split2(sa[2*kkv+1][2], sa[2*kkv+1][3], pah[3], pal[3]);
            uint32_t vh_[8][2], vl_[8][2], t4[4];
#pragma unroll
            for (int p = 0; p < 4; p++) {
                int nr = p * 16 + brow;
                uint32_t a = st + 16384 + nr * 128 + (((kkv*16 + bkh)*2) ^ ((nr & 7) << 4));
                ldm_x4(t4, a);
                vh_[2*p][0] = t4[0]; vh_[2*p][1] = t4[1];
                vh_[2*p+1][0] = t4[2]; vh_[2*p+1][1] = t4[3];
                ldm_x4(t4, a + 8192);
                vl_[2*p][0] = t4[0]; vl_[2*p][1] = t4[1];
                vl_[2*p+1][0] = t4[2]; vl_[2*p+1][1] = t4[3];
            }
#pragma unroll
            for (int nv = 0; nv < 8; nv++) {
                mma16816(co[nv], pah, vh_[nv]);
                mma16816(co[nv], pah, vl_[nv]);
                mma16816(co[nv], pal, vh_[nv]);
            }
        }
        __syncthreads();
    }

    // Epilogue: out[b, s, h*64+d] = O / l
    float inv0 = 1.0f / l0, inv1 = 1.0f / l1;
    int s0 = qt * 64 + wm + (lane >> 2);
#pragma unroll
    for (int nv = 0; nv < 8; nv++) {
        int d = nv * 8 + ((lane & 3) << 1);
        float2* p0 = (float2*)&out[((size_t)b*NS + s0)*NN + h*ND + d];
        *p0 = make_float2(co[nv][0]*inv0, co[nv][1]*inv0);
        float2* p1 = (float2*)&out[((size_t)b*NS + s0 + 8)*NN + h*ND + d];
        *p1 = make_float2(co[nv][2]*inv1, co[nv][3]*inv1);
    }
}

// ---------------------------------------------------------------------------
extern "C" void kernel_launch(void* const* d_in, const int* in_sizes, int n_in,
                              void* d_out, int out_size)
{
    (void)in_sizes; (void)n_in; (void)out_size;
    const float* x_q  = (const float*)d_in[0];
    const float* x_kv = (const float*)d_in[1];
    const float* w_q = (const float*)d_in[3];
    const float* b_q = (const float*)d_in[4];
    const float* w_k = (const float*)d_in[5];
    const float* b_k = (const float*)d_in[6];
    const float* w_v = (const float*)d_in[7];
    const float* b_v = (const float*)d_in[8];
    float* out = (float*)d_out;

    __nv_bfloat16 *xqh, *xql, *xkh, *xkl, *wqh, *wql, *wkh, *wkl, *wvh, *wvl;
    cudaGetSymbolAddress((void**)&xqh, g_xq_h);  cudaGetSymbolAddress((void**)&xql, g_xq_l);
    cudaGetSymbolAddress((void**)&xkh, g_xkv_h); cudaGetSymbolAddress((void**)&xkl, g_xkv_l);
    cudaGetSymbolAddress((void**)&wqh, g_wq_h);  cudaGetSymbolAddress((void**)&wql, g_wq_l);
    cudaGetSymbolAddress((void**)&wkh, g_wk_h);  cudaGetSymbolAddress((void**)&wkl, g_wk_l);
    cudaGetSymbolAddress((void**)&wvh, g_wv_h);  cudaGetSymbolAddress((void**)&wvl, g_wv_l);
    __nv_bfloat16 *qH, *qL, *kH, *kL, *vH, *vL;
    cudaGetSymbolAddress((void**)&qH, g_Qh); cudaGetSymbolAddress((void**)&qL, g_Ql);
    cudaGetSymbolAddress((void**)&kH, g_Kh); cudaGetSymbolAddress((void**)&kL, g_Kl);
    cudaGetSymbolAddress((void**)&vH, g_Vh); cudaGetSymbolAddress((void**)&vL, g_Vl);

    const int nx4 = NM*NE/4, nw4 = NN*NE/4;
    split_kernel<<<(nx4+255)/256, 256>>>(x_q,  xqh, xql, nx4);
    split_kernel<<<(nx4+255)/256, 256>>>(x_kv, xkh, xkl, nx4);
    split_kernel<<<(nw4+255)/256, 256>>>(w_q,  wqh, wql, nw4);
    split_kernel<<<(nw4+255)/256, 256>>>(w_k,  wkh, wkl, nw4);
    split_kernel<<<(nw4+255)/256, 256>>>(w_v,  wvh, wvl, nw4);

    const int psmem = 2 * 65536;
    cudaFuncSetAttribute(proj_kernel, cudaFuncAttributeMaxDynamicSharedMemorySize, psmem);
    dim3 pg(NN/128, NM/128, 3);   // 1536 CTAs, one fused launch
    proj_kernel<<<pg, 256, psmem>>>(xqh, xql, xkh, xkl,
                                    wqh, wql, wkh, wkl, wvh, wvl,
                                    b_q, b_k, b_v,
                                    qH, qL, kH, kL, vH, vL);

    const int asmem = 16384 + 2*32768;   // 81920
    cudaFuncSetAttribute(attn_kernel, cudaFuncAttributeMaxDynamicSharedMemorySize, asmem);
    attn_kernel<<<dim3(NS/64, NH, NB), 128, asmem>>>(out);
}